// round 1
// baseline (speedup 1.0000x reference)
#include <cuda_runtime.h>
#include <math.h>

// Problem constants
#define Bc    2
#define Sc    2048
#define Ec    2048
#define Hc    16
#define HDc   128
#define Mrows 4096     // B*S
#define QKV_N 6144     // 3*E

// Scratch (device globals: allocation-free per harness rules)
__device__ float g_qkv[(size_t)Mrows * QKV_N];   // ~100 MB
__device__ float g_attn[(size_t)Mrows * Ec];     // ~33 MB

// ---------------------------------------------------------------------------
// SGEMM: C[M,N] = A[M,K] @ B[N,K]^T + bias[N]   (both A and B are K-major)
// 128x128 block tile, BK=16, 256 threads, 8x8 per thread.
// ---------------------------------------------------------------------------
__global__ __launch_bounds__(256)
void sgemm_nt_bias(const float* __restrict__ A,
                   const float* __restrict__ Bw,
                   const float* __restrict__ bias,
                   float* __restrict__ C,
                   int Ndim, int Kdim)
{
    __shared__ float As[16][128];
    __shared__ float Bs[16][128];
    const int tid = threadIdx.x;
    const int ty = tid >> 4, tx = tid & 15;
    const int bm = blockIdx.y << 7, bn = blockIdx.x << 7;

    float acc[8][8];
#pragma unroll
    for (int i = 0; i < 8; i++)
#pragma unroll
        for (int j = 0; j < 8; j++) acc[i][j] = 0.f;

    for (int k0 = 0; k0 < Kdim; k0 += 16) {
#pragma unroll
        for (int i = 0; i < 2; i++) {
            int idx = tid + (i << 8);          // 0..511
            int r   = idx >> 2;                // 0..127
            int c4  = (idx & 3) << 2;          // 0,4,8,12
            float4 a = *(const float4*)&A[(size_t)(bm + r) * Kdim + k0 + c4];
            As[c4+0][r] = a.x; As[c4+1][r] = a.y; As[c4+2][r] = a.z; As[c4+3][r] = a.w;
            float4 b = *(const float4*)&Bw[(size_t)(bn + r) * Kdim + k0 + c4];
            Bs[c4+0][r] = b.x; Bs[c4+1][r] = b.y; Bs[c4+2][r] = b.z; Bs[c4+3][r] = b.w;
        }
        __syncthreads();
#pragma unroll
        for (int k = 0; k < 16; k++) {
            float4 a0 = *(const float4*)&As[k][ty*8];
            float4 a1 = *(const float4*)&As[k][ty*8+4];
            float4 b0 = *(const float4*)&Bs[k][tx*8];
            float4 b1 = *(const float4*)&Bs[k][tx*8+4];
            float ar[8] = {a0.x,a0.y,a0.z,a0.w,a1.x,a1.y,a1.z,a1.w};
            float br[8] = {b0.x,b0.y,b0.z,b0.w,b1.x,b1.y,b1.z,b1.w};
#pragma unroll
            for (int i = 0; i < 8; i++)
#pragma unroll
                for (int j = 0; j < 8; j++)
                    acc[i][j] += ar[i] * br[j];
        }
        __syncthreads();
    }

    float bb[8];
#pragma unroll
    for (int j = 0; j < 8; j++) bb[j] = bias[bn + tx*8 + j];
#pragma unroll
    for (int i = 0; i < 8; i++) {
        size_t row = (size_t)(bm + ty*8 + i);
        float4 c0 = make_float4(acc[i][0]+bb[0], acc[i][1]+bb[1],
                                acc[i][2]+bb[2], acc[i][3]+bb[3]);
        float4 c1 = make_float4(acc[i][4]+bb[4], acc[i][5]+bb[5],
                                acc[i][6]+bb[6], acc[i][7]+bb[7]);
        *(float4*)&C[row * Ndim + bn + tx*8    ] = c0;
        *(float4*)&C[row * Ndim + bn + tx*8 + 4] = c1;
    }
}

// ---------------------------------------------------------------------------
// Flash attention, fp32. One CTA per (b, h, 128-query block).
// qkv layout per row m = b*S+s: [h*384 + {0..127 q, 128..255 k, 256..383 v}]
// Online softmax over key tiles of 64. scores scaled by *sqrt(HD) (per ref!).
// ---------------------------------------------------------------------------
#define SQt 128
#define SKt 64
#define DP  132   // padded row stride (floats) for Q/K/V tiles

__global__ __launch_bounds__(256)
void flash_fp32()
{
    extern __shared__ float smf[];
    float* Qs   = smf;                    // 128*132
    float* Ks   = Qs  + SQt*DP;           // 64*132
    float* Vs   = Ks  + SKt*DP;           // 64*132
    float* Ps   = Vs  + SKt*DP;           // 128*64 scores/probs
    float* m_s  = Ps  + SQt*SKt;          // 128
    float* l_s  = m_s + SQt;              // 128
    float* al_s = l_s + SQt;              // 128

    const int tid  = threadIdx.x;
    const int lane = tid & 31, wid = tid >> 5;
    const int ty   = tid >> 4, tx  = tid & 15;
    const int b = blockIdx.z, h = blockIdx.y;
    const int q0 = blockIdx.x << 7;

    const size_t qbase = ((size_t)(b*Sc + q0)) * QKV_N + h*384;

    // Load Q tile (128 x 128)
#pragma unroll
    for (int i = 0; i < 16; i++) {
        int idx = tid + (i << 8);
        int r   = idx >> 5;
        int c4  = (idx & 31) << 2;
        *(float4*)&Qs[r*DP + c4] =
            *(const float4*)&g_qkv[qbase + (size_t)r*QKV_N + c4];
    }
    if (tid < SQt) { m_s[tid] = -INFINITY; l_s[tid] = 0.f; }

    float o[8][8];
#pragma unroll
    for (int i = 0; i < 8; i++)
#pragma unroll
        for (int c = 0; c < 8; c++) o[i][c] = 0.f;

    const float scale = 11.3137084989847604f;  // HD**0.5 (reference MULTIPLIES)

    for (int kt = 0; kt < Sc; kt += SKt) {
        __syncthreads();  // prior PV done with Ks/Vs/Ps; also covers Q/state init
        const size_t kbase = ((size_t)(b*Sc + kt)) * QKV_N + h*384;
#pragma unroll
        for (int i = 0; i < 8; i++) {
            int idx = tid + (i << 8);
            int r   = idx >> 5;
            int c4  = (idx & 31) << 2;
            *(float4*)&Ks[r*DP + c4] =
                *(const float4*)&g_qkv[kbase + (size_t)r*QKV_N + 128 + c4];
            *(float4*)&Vs[r*DP + c4] =
                *(const float4*)&g_qkv[kbase + (size_t)r*QKV_N + 256 + c4];
        }
        __syncthreads();

        // ---- S = Q @ K^T (rows 8*ty+i, cols tx+16*c) ----
        float s[8][4];
#pragma unroll
        for (int i = 0; i < 8; i++)
#pragma unroll
            for (int c = 0; c < 4; c++) s[i][c] = 0.f;

#pragma unroll 8
        for (int d = 0; d < HDc; d += 4) {
            float4 kf[4];
#pragma unroll
            for (int c = 0; c < 4; c++)
                kf[c] = *(const float4*)&Ks[(tx + 16*c)*DP + d];
#pragma unroll
            for (int i = 0; i < 8; i++) {
                float4 qf = *(const float4*)&Qs[(8*ty + i)*DP + d];
#pragma unroll
                for (int c = 0; c < 4; c++)
                    s[i][c] += qf.x*kf[c].x + qf.y*kf[c].y
                             + qf.z*kf[c].z + qf.w*kf[c].w;
            }
        }
#pragma unroll
        for (int i = 0; i < 8; i++)
#pragma unroll
            for (int c = 0; c < 4; c++)
                Ps[(8*ty + i)*SKt + tx + 16*c] = s[i][c] * scale;
        __syncthreads();

        // ---- Online softmax: warp `wid` handles rows 16*wid..16*wid+15 ----
#pragma unroll 1
        for (int rr = 0; rr < 16; rr++) {
            int r = wid*16 + rr;
            float s0 = Ps[r*SKt + lane];
            float s1 = Ps[r*SKt + 32 + lane];
            float mx = fmaxf(s0, s1);
#pragma unroll
            for (int off = 16; off > 0; off >>= 1)
                mx = fmaxf(mx, __shfl_xor_sync(0xffffffffu, mx, off));
            float mo = m_s[r];
            float mn = fmaxf(mo, mx);
            float p0 = __expf(s0 - mn);
            float p1 = __expf(s1 - mn);
            float ps = p0 + p1;
#pragma unroll
            for (int off = 16; off > 0; off >>= 1)
                ps += __shfl_xor_sync(0xffffffffu, ps, off);
            Ps[r*SKt + lane]      = p0;
            Ps[r*SKt + 32 + lane] = p1;
            if (lane == 0) {
                float al = (mo == -INFINITY) ? 0.f : __expf(mo - mn);
                al_s[r] = al;
                l_s[r]  = l_s[r]*al + ps;
                m_s[r]  = mn;
            }
        }
        __syncthreads();

        // ---- O = O*alpha + P @ V (rows 8*ty+i, cols tx+16*c) ----
        float al[8];
#pragma unroll
        for (int i = 0; i < 8; i++) al[i] = al_s[8*ty + i];
#pragma unroll
        for (int i = 0; i < 8; i++)
#pragma unroll
            for (int c = 0; c < 8; c++) o[i][c] *= al[i];

#pragma unroll 4
        for (int j = 0; j < SKt; j++) {
            float p[8], v[8];
#pragma unroll
            for (int i = 0; i < 8; i++) p[i] = Ps[(8*ty + i)*SKt + j];
#pragma unroll
            for (int c = 0; c < 8; c++) v[c] = Vs[j*DP + tx + 16*c];
#pragma unroll
            for (int i = 0; i < 8; i++)
#pragma unroll
                for (int c = 0; c < 8; c++)
                    o[i][c] += p[i]*v[c];
        }
    }

    // Epilogue: normalize and scatter to (b, s, h*HD + d) layout
#pragma unroll
    for (int i = 0; i < 8; i++) {
        int r = 8*ty + i;
        float inv = 1.0f / l_s[r];
        size_t obase = ((size_t)(b*Sc + q0 + r)) * Ec + h*HDc;
#pragma unroll
        for (int c = 0; c < 8; c++)
            g_attn[obase + tx + 16*c] = o[i][c] * inv;
    }
}

// ---------------------------------------------------------------------------
extern "C" void kernel_launch(void* const* d_in, const int* in_sizes, int n_in,
                              void* d_out, int out_size)
{
    const float* query = (const float*)d_in[0];
    // d_in[1]=key, d_in[2]=value: unused by the reference computation
    const float* Wqkv  = (const float*)d_in[3];
    const float* bqkv  = (const float*)d_in[4];
    const float* Wproj = (const float*)d_in[5];
    const float* bproj = (const float*)d_in[6];
    float* out = (float*)d_out;

    float *qkvp = nullptr, *attnp = nullptr;
    cudaGetSymbolAddress((void**)&qkvp,  g_qkv);
    cudaGetSymbolAddress((void**)&attnp, g_attn);

    // 1) qkv = query @ Wqkv^T + bqkv
    sgemm_nt_bias<<<dim3(QKV_N/128, Mrows/128), 256>>>(
        query, Wqkv, bqkv, qkvp, QKV_N, Ec);

    // 2) flash attention -> g_attn (b, s, E) layout
    const int smem_bytes = (SQt*DP + 2*SKt*DP + SQt*SKt + 3*SQt) * (int)sizeof(float);
    cudaFuncSetAttribute(flash_fp32,
                         cudaFuncAttributeMaxDynamicSharedMemorySize, smem_bytes);
    flash_fp32<<<dim3(Sc/128, Hc, Bc), 256, smem_bytes>>>();

    // 3) out = attn @ Wproj^T + bproj
    sgemm_nt_bias<<<dim3(Ec/128, Mrows/128), 256>>>(
        attnp, Wproj, bproj, out, Ec, Ec);
}

// round 2
// speedup vs baseline: 1.0650x; 1.0650x over previous
#include <cuda_runtime.h>
#include <math.h>
#include <stdint.h>

// Problem constants
#define Bc    2
#define Sc    2048
#define Ec    2048
#define Hc    16
#define HDc   128
#define Mrows 4096     // B*S
#define QKV_N 6144     // 3*E
#define GK    2048     // K dim of both GEMMs

// Scratch (device globals: allocation-free per harness rules)
__device__ float g_qkv[(size_t)Mrows * QKV_N];   // ~100 MB
__device__ float g_attn[(size_t)Mrows * Ec];     // ~33 MB

// ---------------------------------------------------------------------------
// 3xTF32 tensor-core GEMM: C[M,N] = A[M,K] @ B[N,K]^T + bias[N]
// BM=BN=128, BK=32, 256 threads (8 warps, 2x4), warp tile 64x32.
// A/B split into (hi,lo) tf32 pairs at STS time, packed uint2 in smem.
// ---------------------------------------------------------------------------
#define BKg 32
#define SPAD 36          // row stride (uint2 elements) for conflict-free frags

__device__ __forceinline__ uint32_t f2tf32(float x) {
    uint32_t r;
    asm("cvt.rna.tf32.f32 %0, %1;" : "=r"(r) : "f"(x));
    return r;
}

__device__ __forceinline__ uint2 split_tf32(float x) {
    uint32_t hi = f2tf32(x);
    float lo_f = x - __uint_as_float(hi);
    uint32_t lo = f2tf32(lo_f);
    return make_uint2(hi, lo);
}

__device__ __forceinline__ void mma8(float* c,
                                     uint32_t a0, uint32_t a1, uint32_t a2, uint32_t a3,
                                     uint32_t b0, uint32_t b1) {
    asm volatile(
        "mma.sync.aligned.m16n8k8.row.col.f32.tf32.tf32.f32 "
        "{%0,%1,%2,%3}, {%4,%5,%6,%7}, {%8,%9}, {%0,%1,%2,%3};"
        : "+f"(c[0]), "+f"(c[1]), "+f"(c[2]), "+f"(c[3])
        : "r"(a0), "r"(a1), "r"(a2), "r"(a3), "r"(b0), "r"(b1));
}

__global__ __launch_bounds__(256)
void gemm_tf32x3(const float* __restrict__ A,
                 const float* __restrict__ Bw,
                 const float* __restrict__ bias,
                 float* __restrict__ C,
                 int Ndim)
{
    extern __shared__ uint2 sm2[];
    uint2* As = sm2;                 // [128][SPAD]
    uint2* Bs = sm2 + 128 * SPAD;    // [128][SPAD]

    const int tid   = threadIdx.x;
    const int lane  = tid & 31;
    const int wid   = tid >> 5;
    const int m_off = (wid & 1) << 6;   // 0 or 64
    const int n_off = (wid >> 1) << 5;  // 0,32,64,96
    const int bm    = blockIdx.y << 7;
    const int bn    = blockIdx.x << 7;

    const int row_base = tid >> 3;        // 0..31
    const int col4     = (tid & 7) << 2;  // 0,4,...,28

    float c[4][4][4];
#pragma unroll
    for (int mt = 0; mt < 4; mt++)
#pragma unroll
        for (int nt = 0; nt < 4; nt++)
#pragma unroll
            for (int e = 0; e < 4; e++) c[mt][nt][e] = 0.f;

    float4 pa[4], pb[4];

    // prefetch k-slice 0
#pragma unroll
    for (int i = 0; i < 4; i++) {
        int r = row_base + 32 * i;
        pa[i] = *(const float4*)&A [(size_t)(bm + r) * GK + col4];
        pb[i] = *(const float4*)&Bw[(size_t)(bn + r) * GK + col4];
    }

    const int nsteps = GK / BKg;  // 64
    for (int step = 0; step < nsteps; step++) {
        __syncthreads();  // smem free from previous compute

        // convert + store current slice (hi,lo packed)
#pragma unroll
        for (int i = 0; i < 4; i++) {
            int r = row_base + 32 * i;
            float av[4] = {pa[i].x, pa[i].y, pa[i].z, pa[i].w};
            float bv[4] = {pb[i].x, pb[i].y, pb[i].z, pb[i].w};
            uint2 ah[4], bh[4];
#pragma unroll
            for (int j = 0; j < 4; j++) { ah[j] = split_tf32(av[j]); bh[j] = split_tf32(bv[j]); }
            *(uint4*)&As[r * SPAD + col4    ] = make_uint4(ah[0].x, ah[0].y, ah[1].x, ah[1].y);
            *(uint4*)&As[r * SPAD + col4 + 2] = make_uint4(ah[2].x, ah[2].y, ah[3].x, ah[3].y);
            *(uint4*)&Bs[r * SPAD + col4    ] = make_uint4(bh[0].x, bh[0].y, bh[1].x, bh[1].y);
            *(uint4*)&Bs[r * SPAD + col4 + 2] = make_uint4(bh[2].x, bh[2].y, bh[3].x, bh[3].y);
        }
        __syncthreads();

        // prefetch next slice (overlaps with MMA below)
        if (step + 1 < nsteps) {
            int k0 = (step + 1) * BKg;
#pragma unroll
            for (int i = 0; i < 4; i++) {
                int r = row_base + 32 * i;
                pa[i] = *(const float4*)&A [(size_t)(bm + r) * GK + k0 + col4];
                pb[i] = *(const float4*)&Bw[(size_t)(bn + r) * GK + k0 + col4];
            }
        }

        // 4 k8 sub-steps
#pragma unroll
        for (int kk = 0; kk < 4; kk++) {
            const int kc = (kk << 3) + (lane & 3);
            uint2 a[4][4];
#pragma unroll
            for (int mt = 0; mt < 4; mt++) {
                int r0 = m_off + mt * 16 + (lane >> 2);
                a[mt][0] = As[r0 * SPAD + kc];
                a[mt][1] = As[(r0 + 8) * SPAD + kc];
                a[mt][2] = As[r0 * SPAD + kc + 4];
                a[mt][3] = As[(r0 + 8) * SPAD + kc + 4];
            }
            uint2 b[4][2];
#pragma unroll
            for (int nt = 0; nt < 4; nt++) {
                int n0 = n_off + nt * 8 + (lane >> 2);
                b[nt][0] = Bs[n0 * SPAD + kc];
                b[nt][1] = Bs[n0 * SPAD + kc + 4];
            }
#pragma unroll
            for (int mt = 0; mt < 4; mt++)
#pragma unroll
                for (int nt = 0; nt < 4; nt++) {
                    // hi*hi, hi*lo, lo*hi
                    mma8(c[mt][nt], a[mt][0].x, a[mt][1].x, a[mt][2].x, a[mt][3].x,
                                    b[nt][0].x, b[nt][1].x);
                    mma8(c[mt][nt], a[mt][0].x, a[mt][1].x, a[mt][2].x, a[mt][3].x,
                                    b[nt][0].y, b[nt][1].y);
                    mma8(c[mt][nt], a[mt][0].y, a[mt][1].y, a[mt][2].y, a[mt][3].y,
                                    b[nt][0].x, b[nt][1].x);
                }
        }
    }

    // epilogue: bias + store (float2 per c-pair)
#pragma unroll
    for (int mt = 0; mt < 4; mt++) {
        int r0 = bm + m_off + mt * 16 + (lane >> 2);
#pragma unroll
        for (int nt = 0; nt < 4; nt++) {
            int col = bn + n_off + nt * 8 + ((lane & 3) << 1);
            float b0 = bias[col], b1 = bias[col + 1];
            *(float2*)&C[(size_t)r0 * Ndim + col] =
                make_float2(c[mt][nt][0] + b0, c[mt][nt][1] + b1);
            *(float2*)&C[(size_t)(r0 + 8) * Ndim + col] =
                make_float2(c[mt][nt][2] + b0, c[mt][nt][3] + b1);
        }
    }
}

// ---------------------------------------------------------------------------
// Flash attention, fp32 (unchanged from R1).
// ---------------------------------------------------------------------------
#define SQt 128
#define SKt 64
#define DP  132

__global__ __launch_bounds__(256)
void flash_fp32()
{
    extern __shared__ float smf[];
    float* Qs   = smf;
    float* Ks   = Qs  + SQt*DP;
    float* Vs   = Ks  + SKt*DP;
    float* Ps   = Vs  + SKt*DP;
    float* m_s  = Ps  + SQt*SKt;
    float* l_s  = m_s + SQt;
    float* al_s = l_s + SQt;

    const int tid  = threadIdx.x;
    const int lane = tid & 31, wid = tid >> 5;
    const int ty   = tid >> 4, tx  = tid & 15;
    const int b = blockIdx.z, h = blockIdx.y;
    const int q0 = blockIdx.x << 7;

    const size_t qbase = ((size_t)(b*Sc + q0)) * QKV_N + h*384;

#pragma unroll
    for (int i = 0; i < 16; i++) {
        int idx = tid + (i << 8);
        int r   = idx >> 5;
        int c4  = (idx & 31) << 2;
        *(float4*)&Qs[r*DP + c4] =
            *(const float4*)&g_qkv[qbase + (size_t)r*QKV_N + c4];
    }
    if (tid < SQt) { m_s[tid] = -INFINITY; l_s[tid] = 0.f; }

    float o[8][8];
#pragma unroll
    for (int i = 0; i < 8; i++)
#pragma unroll
        for (int c = 0; c < 8; c++) o[i][c] = 0.f;

    const float scale = 11.3137084989847604f;  // HD**0.5 (reference MULTIPLIES)

    for (int kt = 0; kt < Sc; kt += SKt) {
        __syncthreads();
        const size_t kbase = ((size_t)(b*Sc + kt)) * QKV_N + h*384;
#pragma unroll
        for (int i = 0; i < 8; i++) {
            int idx = tid + (i << 8);
            int r   = idx >> 5;
            int c4  = (idx & 31) << 2;
            *(float4*)&Ks[r*DP + c4] =
                *(const float4*)&g_qkv[kbase + (size_t)r*QKV_N + 128 + c4];
            *(float4*)&Vs[r*DP + c4] =
                *(const float4*)&g_qkv[kbase + (size_t)r*QKV_N + 256 + c4];
        }
        __syncthreads();

        float s[8][4];
#pragma unroll
        for (int i = 0; i < 8; i++)
#pragma unroll
            for (int c = 0; c < 4; c++) s[i][c] = 0.f;

#pragma unroll 8
        for (int d = 0; d < HDc; d += 4) {
            float4 kf[4];
#pragma unroll
            for (int c = 0; c < 4; c++)
                kf[c] = *(const float4*)&Ks[(tx + 16*c)*DP + d];
#pragma unroll
            for (int i = 0; i < 8; i++) {
                float4 qf = *(const float4*)&Qs[(8*ty + i)*DP + d];
#pragma unroll
                for (int c = 0; c < 4; c++)
                    s[i][c] += qf.x*kf[c].x + qf.y*kf[c].y
                             + qf.z*kf[c].z + qf.w*kf[c].w;
            }
        }
#pragma unroll
        for (int i = 0; i < 8; i++)
#pragma unroll
            for (int c = 0; c < 4; c++)
                Ps[(8*ty + i)*SKt + tx + 16*c] = s[i][c] * scale;
        __syncthreads();

#pragma unroll 1
        for (int rr = 0; rr < 16; rr++) {
            int r = wid*16 + rr;
            float s0 = Ps[r*SKt + lane];
            float s1 = Ps[r*SKt + 32 + lane];
            float mx = fmaxf(s0, s1);
#pragma unroll
            for (int off = 16; off > 0; off >>= 1)
                mx = fmaxf(mx, __shfl_xor_sync(0xffffffffu, mx, off));
            float mo = m_s[r];
            float mn = fmaxf(mo, mx);
            float p0 = __expf(s0 - mn);
            float p1 = __expf(s1 - mn);
            float ps = p0 + p1;
#pragma unroll
            for (int off = 16; off > 0; off >>= 1)
                ps += __shfl_xor_sync(0xffffffffu, ps, off);
            Ps[r*SKt + lane]      = p0;
            Ps[r*SKt + 32 + lane] = p1;
            if (lane == 0) {
                float al = (mo == -INFINITY) ? 0.f : __expf(mo - mn);
                al_s[r] = al;
                l_s[r]  = l_s[r]*al + ps;
                m_s[r]  = mn;
            }
        }
        __syncthreads();

        float al[8];
#pragma unroll
        for (int i = 0; i < 8; i++) al[i] = al_s[8*ty + i];
#pragma unroll
        for (int i = 0; i < 8; i++)
#pragma unroll
            for (int c = 0; c < 8; c++) o[i][c] *= al[i];

#pragma unroll 4
        for (int j = 0; j < SKt; j++) {
            float p[8], v[8];
#pragma unroll
            for (int i = 0; i < 8; i++) p[i] = Ps[(8*ty + i)*SKt + j];
#pragma unroll
            for (int c = 0; c < 8; c++) v[c] = Vs[j*DP + tx + 16*c];
#pragma unroll
            for (int i = 0; i < 8; i++)
#pragma unroll
                for (int c = 0; c < 8; c++)
                    o[i][c] += p[i]*v[c];
        }
    }

#pragma unroll
    for (int i = 0; i < 8; i++) {
        int r = 8*ty + i;
        float inv = 1.0f / l_s[r];
        size_t obase = ((size_t)(b*Sc + q0 + r)) * Ec + h*HDc;
#pragma unroll
        for (int c = 0; c < 8; c++)
            g_attn[obase + tx + 16*c] = o[i][c] * inv;
    }
}

// ---------------------------------------------------------------------------
extern "C" void kernel_launch(void* const* d_in, const int* in_sizes, int n_in,
                              void* d_out, int out_size)
{
    const float* query = (const float*)d_in[0];
    const float* Wqkv  = (const float*)d_in[3];
    const float* bqkv  = (const float*)d_in[4];
    const float* Wproj = (const float*)d_in[5];
    const float* bproj = (const float*)d_in[6];
    float* out = (float*)d_out;

    float *qkvp = nullptr, *attnp = nullptr;
    cudaGetSymbolAddress((void**)&qkvp,  g_qkv);
    cudaGetSymbolAddress((void**)&attnp, g_attn);

    const int gemm_smem = 2 * 128 * SPAD * (int)sizeof(uint2);  // 73728
    cudaFuncSetAttribute(gemm_tf32x3,
                         cudaFuncAttributeMaxDynamicSharedMemorySize, gemm_smem);

    // 1) qkv = query @ Wqkv^T + bqkv   (3xTF32 tensor cores)
    gemm_tf32x3<<<dim3(QKV_N/128, Mrows/128), 256, gemm_smem>>>(
        query, Wqkv, bqkv, qkvp, QKV_N);

    // 2) flash attention -> g_attn
    const int fl_smem = (SQt*DP + 2*SKt*DP + SQt*SKt + 3*SQt) * (int)sizeof(float);
    cudaFuncSetAttribute(flash_fp32,
                         cudaFuncAttributeMaxDynamicSharedMemorySize, fl_smem);
    flash_fp32<<<dim3(Sc/128, Hc, Bc), 256, fl_smem>>>();

    // 3) out = attn @ Wproj^T + bproj  (3xTF32 tensor cores)
    gemm_tf32x3<<<dim3(Ec/128, Mrows/128), 256, gemm_smem>>>(
        attnp, Wproj, bproj, out, Ec);
}